// round 16
// baseline (speedup 1.0000x reference)
#include <cuda_runtime.h>
#include <cuda_bf16.h>
#include <cuda_pipeline.h>

#define B_   64
#define C_   64
#define HW_  4096
#define NTOK (B_*HW_)          // 262144
#define P_   5
#define E_   4
#define HD_  170
#define JP   192               // padded hidden (6 * 32)
#define TOK  256
#define TPB  512
#define NBLK (NTOK/TOK)        // 1024
#define GRID_MAIN 148
#define GA_NBLK 256            // k_gate blocks (1024 tokens each)

// ---------------- scratch (static __device__, allocation-free) ----------------
__device__ float g_emb[B_*C_];
__device__ float g_pw[B_*P_];
__device__ float g_impP[GA_NBLK*E_];
__device__ float g_loadP[GA_NBLK*E_];
__device__ uint4 g_xT4[(size_t)NTOK*64/16];     // fp8 x^T [tok][64c], 16 MB
__device__ uint4 g_gp4[(size_t)NBLK*256];       // fp32 gates [tile][4][256]
// fp8 weights (scaled x16), packed k-pairs as u16 elements, K-permuted (see k_prep)
__device__ uint4 g_wcP4[32*64*2/16];        // [kp=c/2][o]        (conv B, natural)
__device__ uint4 g_w1P4[E_*32*JP*2/16];     // [e][kp PERM][j 192]
__device__ uint4 g_w2P4[E_*96*64*2/16];     // [e][jp PERM][o]

#define SW  16.0f                // weight scale
#define SOT 128.0f               // OT scale
#define SH  4096.0f              // H scale

__device__ __forceinline__ float gelu_f(float z) {
    float u = z * (0.7978845608028654f + 0.03567740814f * z * z);
    float t;
    asm("tanh.approx.f32 %0, %1;" : "=f"(t) : "f"(u));
    return fmaf(0.5f * z, t, 0.5f * z);
}
__device__ __forceinline__ unsigned pack_e4m3(float lo, float hi) {
    unsigned short u;
    asm("cvt.rn.satfinite.e4m3x2.f32 %0, %1, %2;" : "=h"(u) : "f"(hi), "f"(lo));
    return (unsigned)u;
}
__device__ __forceinline__ unsigned pack4_e4m3(float a, float b, float c, float d) {
    return pack_e4m3(a, b) | (pack_e4m3(c, d) << 16);
}

// ---------------- K0: weight prep (fp32 -> scaled fp8 pairs, K-permuted) --------
__global__ void k_prep(const float* __restrict__ w_conv,
                       const float* __restrict__ w1,
                       const float* __restrict__ w2) {
    int i = blockIdx.x * blockDim.x + threadIdx.x;
    unsigned short* wc = (unsigned short*)g_wcP4;
    unsigned short* w1p = (unsigned short*)g_w1P4;
    unsigned short* w2p = (unsigned short*)g_w2P4;
    const int NWC = 32*64, NW1 = E_*32*JP, NW2 = E_*96*64;
    if (i < NWC) {
        int kp = i >> 6, o = i & 63;    // conv K natural
        wc[i] = (unsigned short)pack_e4m3(w_conv[o*C_ + 2*kp] * SW,
                                          w_conv[o*C_ + 2*kp + 1] * SW);
    } else if (i < NWC + NW1) {
        int r = i - NWC;
        int e = r / (32*JP); int r2 = r % (32*JP);
        int kp = r2 / JP;    int j  = r2 % JP;
        int c0 = 8*(kp & 7) + 2*(kp >> 3);   // permuted source channels
        float lo = (j < HD_) ? w1[((size_t)e*C_ + c0    )*HD_ + j] * SW : 0.f;
        float hi = (j < HD_) ? w1[((size_t)e*C_ + c0 + 1)*HD_ + j] * SW : 0.f;
        w1p[r] = (unsigned short)pack_e4m3(lo, hi);
    } else if (i < NWC + NW1 + NW2) {
        int r = i - NWC - NW1;
        int e = r / (96*64); int r2 = r % (96*64);
        int jp = r2 / 64;    int o  = r2 % 64;
        int s = jp >> 5, t = jp & 31;
        int j0 = s*64 + 8*(t & 7) + 2*(t >> 3);   // permuted source j
        float lo = (j0     < HD_) ? w2[((size_t)e*HD_ + j0    )*C_ + o] * SW : 0.f;
        float hi = (j0 + 1 < HD_) ? w2[((size_t)e*HD_ + j0 + 1)*C_ + o] * SW : 0.f;
        w2p[r] = (unsigned short)pack_e4m3(lo, hi);
    }
}

// ---------------- K_gate: exact gating + loss partials + fp8 x^T ----------------
#define GA_TPB 256
__global__ void __launch_bounds__(GA_TPB) k_gate(
    const float* __restrict__ x, const float* __restrict__ w_gate)
{
    __shared__ float sI[8][E_];
    __shared__ float sC[8][E_];
    const int tid = threadIdx.x, blk = blockIdx.x;
    const int bimg = blk >> 2, hw0 = (blk & 3) * 1024;
    const size_t xbase = (size_t)bimg * (C_*HW_);
    const int tloc = tid * 4;
    const float* xp = x + xbase + hw0 + tloc;

    float l[E_][4];
    #pragma unroll
    for (int e = 0; e < E_; e++)
        #pragma unroll
        for (int k = 0; k < 4; k++) l[e][k] = 0.f;
    unsigned xr[4][16];

    #pragma unroll
    for (int cq = 0; cq < 16; cq++) {
        float4 v0 = *(const float4*)(xp + (size_t)(4*cq    )*HW_);
        float4 v1 = *(const float4*)(xp + (size_t)(4*cq + 1)*HW_);
        float4 v2 = *(const float4*)(xp + (size_t)(4*cq + 2)*HW_);
        float4 v3 = *(const float4*)(xp + (size_t)(4*cq + 3)*HW_);
        float4 w0 = *(const float4*)(w_gate + (4*cq    )*4);
        float4 w1v = *(const float4*)(w_gate + (4*cq + 1)*4);
        float4 w2v = *(const float4*)(w_gate + (4*cq + 2)*4);
        float4 w3 = *(const float4*)(w_gate + (4*cq + 3)*4);
        const float* pv0 = &v0.x; const float* pv1 = &v1.x;
        const float* pv2 = &v2.x; const float* pv3 = &v3.x;
        #pragma unroll
        for (int k = 0; k < 4; k++) {
            float a0 = pv0[k], a1 = pv1[k], a2 = pv2[k], a3 = pv3[k];
            l[0][k] += a0*w0.x + a1*w1v.x + a2*w2v.x + a3*w3.x;
            l[1][k] += a0*w0.y + a1*w1v.y + a2*w2v.y + a3*w3.y;
            l[2][k] += a0*w0.z + a1*w1v.z + a2*w2v.z + a3*w3.z;
            l[3][k] += a0*w0.w + a1*w1v.w + a2*w2v.w + a3*w3.w;
            xr[k][cq] = pack4_e4m3(a0, a1, a2, a3);
        }
    }
    {
        size_t gtok = (size_t)bimg*4096 + hw0 + tloc;
        uint4* dst = g_xT4 + gtok * 4;
        #pragma unroll
        for (int k = 0; k < 4; k++) {
            dst[k*4 + 0] = make_uint4(xr[k][0],  xr[k][1],  xr[k][2],  xr[k][3]);
            dst[k*4 + 1] = make_uint4(xr[k][4],  xr[k][5],  xr[k][6],  xr[k][7]);
            dst[k*4 + 2] = make_uint4(xr[k][8],  xr[k][9],  xr[k][10], xr[k][11]);
            dst[k*4 + 3] = make_uint4(xr[k][12], xr[k][13], xr[k][14], xr[k][15]);
        }
    }
    float gA[E_][4];
    float impA[E_] = {0.f, 0.f, 0.f, 0.f};
    float cntA[E_] = {0.f, 0.f, 0.f, 0.f};
    #pragma unroll
    for (int k = 0; k < 4; k++) {
        float lv[E_] = { l[0][k], l[1][k], l[2][k], l[3][k] };
        float v1m = -1e30f, v2m = -1e30f; int i1 = 0, i2 = 0;
        #pragma unroll
        for (int e = 0; e < E_; e++) {
            if (lv[e] > v1m) { v2m = v1m; i2 = i1; v1m = lv[e]; i1 = e; }
            else if (lv[e] > v2m) { v2m = lv[e]; i2 = e; }
        }
        float g1 = 1.0f / (1.0f + expf(v2m - v1m));
        float g2 = 1.0f - g1;
        #pragma unroll
        for (int e = 0; e < E_; e++)
            gA[e][k] = (e == i1) ? g1 : ((e == i2) ? g2 : 0.f);
        impA[i1] += g1; impA[i2] += g2;
        cntA[i1] += 1.f; cntA[i2] += 1.f;
    }
    {
        int gtok = bimg*4096 + hw0 + tloc;
        int tile = gtok >> 8, tin = gtok & 255;
        float* gpf = (float*)g_gp4 + (size_t)tile*1024 + tin;
        #pragma unroll
        for (int e = 0; e < E_; e++)
            *(float4*)(gpf + e*256) = make_float4(gA[e][0], gA[e][1], gA[e][2], gA[e][3]);
    }
    int warp = tid >> 5, lane = tid & 31;
    #pragma unroll
    for (int e = 0; e < E_; e++) {
        float im = impA[e], cn = cntA[e];
        #pragma unroll
        for (int o = 16; o; o >>= 1) {
            im += __shfl_xor_sync(0xffffffffu, im, o);
            cn += __shfl_xor_sync(0xffffffffu, cn, o);
        }
        if (lane == 0) { sI[warp][e] = im; sC[warp][e] = cn; }
    }
    __syncthreads();
    if (tid < E_) {
        float im = 0.f, cn = 0.f;
        #pragma unroll
        for (int w = 0; w < 8; w++) { im += sI[w][tid]; cn += sC[w][tid]; }
        g_impP[blk*E_ + tid]  = im;
        g_loadP[blk*E_ + tid] = cn;
    }
}

// ---------------- K_emb8: emb from fp8 x^T ----------------
__global__ void __launch_bounds__(256) k_emb8() {
    __shared__ float part[8][64];
    const int b = blockIdx.x, tid = threadIdx.x;
    const int warp = tid >> 5, lane = tid & 31;
    float acc[64];
    #pragma unroll
    for (int c = 0; c < 64; c++) acc[c] = 0.f;
    const uint4* base = g_xT4 + (size_t)b * 4096 * 4;
    for (int row = tid; row < 4096; row += 256) {
        const uint4* rp = base + row*4;
        #pragma unroll
        for (int u4 = 0; u4 < 4; u4++) {
            uint4 v = rp[u4];
            unsigned w[4] = { v.x, v.y, v.z, v.w };
            #pragma unroll
            for (int k = 0; k < 4; k++) {
                unsigned lo16 = w[k] & 0xffffu, hi16 = w[k] >> 16;
                unsigned h2a, h2b;
                asm("cvt.rn.f16x2.e4m3x2 %0, %1;" : "=r"(h2a) : "h"((unsigned short)lo16));
                asm("cvt.rn.f16x2.e4m3x2 %0, %1;" : "=r"(h2b) : "h"((unsigned short)hi16));
                float2 fa = __half22float2(*(__half2*)&h2a);
                float2 fb = __half22float2(*(__half2*)&h2b);
                int c0 = u4*16 + k*4;
                acc[c0]   += fa.x; acc[c0+1] += fa.y;
                acc[c0+2] += fb.x; acc[c0+3] += fb.y;
            }
        }
    }
    #pragma unroll
    for (int c = 0; c < 64; c++) {
        float s = acc[c];
        #pragma unroll
        for (int o = 16; o; o >>= 1) s += __shfl_xor_sync(0xffffffffu, s, o);
        if (lane == 0) part[warp][c] = s;
    }
    __syncthreads();
    if (tid < 64) {
        float s = 0.f;
        #pragma unroll
        for (int w = 0; w < 8; w++) s += part[w][tid];
        g_emb[b*64 + tid] = s * (1.0f / HW_);
    }
}

// ---------------- K2: pw ----------------
__global__ void k_pw(const float* __restrict__ w_lin, const float* __restrict__ b_lin) {
    int b = blockIdx.x, c = threadIdx.x;   // 64 threads
    __shared__ float red[2][P_];
    float e = g_emb[b*C_ + c];
    float lg[P_];
    #pragma unroll
    for (int p = 0; p < P_; p++) lg[p] = e * w_lin[c*P_ + p];
    #pragma unroll
    for (int o = 16; o; o >>= 1)
        #pragma unroll
        for (int p = 0; p < P_; p++) lg[p] += __shfl_xor_sync(0xffffffffu, lg[p], o);
    if ((c & 31) == 0)
        #pragma unroll
        for (int p = 0; p < P_; p++) red[c >> 5][p] = lg[p];
    __syncthreads();
    if (c == 0) {
        float v[P_];
        #pragma unroll
        for (int p = 0; p < P_; p++) v[p] = red[0][p] + red[1][p] + b_lin[p];
        float mx = v[0];
        #pragma unroll
        for (int p = 1; p < P_; p++) mx = fmaxf(mx, v[p]);
        float s = 0.f;
        #pragma unroll
        for (int p = 0; p < P_; p++) { v[p] = expf(v[p] - mx); s += v[p]; }
        float inv = 1.0f / s;
        #pragma unroll
        for (int p = 0; p < P_; p++) g_pw[b*P_ + p] = v[p] * inv;
    }
}

// ---------------- mma helpers ----------------
__device__ __forceinline__ void mma_f8(float* c, const unsigned* a, const unsigned* b) {
    asm volatile(
        "mma.sync.aligned.m16n8k32.row.col.f32.e4m3.e4m3.f32 "
        "{%0,%1,%2,%3},{%4,%5,%6,%7},{%8,%9},{%0,%1,%2,%3};\n"
        : "+f"(c[0]), "+f"(c[1]), "+f"(c[2]), "+f"(c[3])
        : "r"(a[0]), "r"(a[1]), "r"(a[2]), "r"(a[3]), "r"(b[0]), "r"(b[1]));
}
__device__ __forceinline__ void ldmA(unsigned* a, unsigned addr) {
    asm volatile("ldmatrix.sync.aligned.m8n8.x4.shared.b16 {%0,%1,%2,%3},[%4];\n"
        : "=r"(a[0]), "=r"(a[1]), "=r"(a[2]), "=r"(a[3]) : "r"(addr));
}
__device__ __forceinline__ void ldmBT(unsigned* b, unsigned addr) {
    asm volatile("ldmatrix.sync.aligned.m8n8.x4.trans.shared.b16 {%0,%1,%2,%3},[%4];\n"
        : "=r"(b[0]), "=r"(b[1]), "=r"(b[2]), "=r"(b[3]) : "r"(addr));
}

// ---------------- k_main smem layout (bytes) ----------------
#define XT_OFF  0               // 2 x (256 rows * 80B) = 40960
#define GT_OFF  40960           // 2 x 4096 (gates)
#define W1_OFF  49152           // 4 x 12800 (u16 [32 kp][192 j], pitch 400B)
#define W2_OFF  100352          // 4 x 13824 (u16 [96 jp][64 o], pitch 144B)
#define WC_OFF  155648          // u16 [32 kp][64 o], pitch 144B = 4608
#define B1_OFF  160256          // fp32 [4][192] = 3072
#define B2_OFF  163328          // fp32 [4][64] = 1024
#define SC_OFF  164352          // per-warp scratch 40960B; Ys bf16 [64][528B] overlays it in epilogue
#define YS_PITCH 528
#define SMEM_MAIN 205312

__device__ __forceinline__ void stage_tile(char* smem, int buf, int tile, int tid) {
    const uint4* src = g_xT4 + (size_t)tile * (TOK*4);
    for (int u = tid; u < TOK*4; u += TPB) {
        int row = u >> 2, un = u & 3;
        __pipeline_memcpy_async(smem + XT_OFF + buf*20480 + row*80 + un*16, src + u, 16);
    }
    const uint4* gsrc = g_gp4 + (size_t)tile * 256;
    for (int u = tid; u < 256; u += TPB)
        __pipeline_memcpy_async(smem + GT_OFF + buf*4096 + u*16, gsrc + u, 16);
}

__global__ void __launch_bounds__(TPB, 1) k_main(
    const float* __restrict__ x, const float* __restrict__ sp,
    const float* __restrict__ b1, const float* __restrict__ b2,
    float* __restrict__ out)
{
    extern __shared__ char smem[];
    unsigned sbase = (unsigned)__cvta_generic_to_shared(smem);
    float* b1s = (float*)(smem + B1_OFF);
    float* b2s = (float*)(smem + B2_OFF);

    const int tid  = threadIdx.x;
    const int lane = tid & 31, warp = tid >> 5;
    const int r = lane & 7, q = lane >> 3;
    const int g_ = lane >> 2, tg = lane & 3;
    const int m0 = warp * 16, ta = m0 + g_, tb = ta + 8;
    const unsigned scr0 = sbase + SC_OFF + warp*2560;        // parity-0 buffer
    char* scw0 = smem + SC_OFF + warp*2560;
    const unsigned ldrow = (unsigned)(r + (q&1)*8);
    const unsigned ldsel = (unsigned)(q >> 1);

    // ---- one-time staging: all weights + first tile ----
    for (int u = tid; u < 32*8; u += TPB) {
        int row = u >> 3, un = u & 7;
        __pipeline_memcpy_async(smem + WC_OFF + row*144 + un*16, g_wcP4 + u, 16);
    }
    for (int u = tid; u < E_*32*24; u += TPB) {
        int e = u / (32*24), v = u % (32*24);
        int row = v / 24, un = v % 24;
        __pipeline_memcpy_async(smem + W1_OFF + e*12800 + row*400 + un*16, g_w1P4 + u, 16);
    }
    for (int u = tid; u < E_*96*8; u += TPB) {
        int e = u / (96*8), v = u % (96*8);
        int row = v >> 3, un = v & 7;
        __pipeline_memcpy_async(smem + W2_OFF + e*13824 + row*144 + un*16, g_w2P4 + u, 16);
    }
    stage_tile(smem, 0, blockIdx.x, tid);
    __pipeline_commit();
    for (int i = tid; i < E_*JP; i += TPB) {
        int e = i / JP, j = i % JP;
        b1s[i] = (j < HD_) ? b1[e*HD_ + j] : 0.f;
    }
    if (tid < E_*C_) b2s[tid] = b2[tid];
    __pipeline_wait_prior(0);
    __syncthreads();

    const float INV1 = 1.0f / (SOT * SW);
    const float INV2 = 1.0f / (SH * SW);

    int buf = 0;
    for (int tile = blockIdx.x; tile < NBLK; tile += GRID_MAIN) {
        const int bimg = tile >> 4;
        const int hw0  = (tile & 15) * TOK;
        const size_t xbase = (size_t)bimg * (C_*HW_);
        const float* gtp = (float*)(smem + GT_OFF + buf*4096);

        float ge0[E_], ge1[E_];
        #pragma unroll
        for (int e = 0; e < E_; e++) {
            ge0[e] = gtp[e*TOK + ta];
            ge1[e] = gtp[e*TOK + tb];
        }
        float pr0 = 0.f, pr1 = 0.f;
        #pragma unroll
        for (int p = 0; p < P_; p++) {
            float pwv = g_pw[bimg*P_ + p];
            pr0 = fmaf(pwv, sp[p*HW_ + hw0 + ta], pr0);
            pr1 = fmaf(pwv, sp[p*HW_ + hw0 + tb], pr1);
        }
        pr0 *= (SOT / SW);
        pr1 *= (SOT / SW);

        // ---- conv (writes scratch parity 0, permuted K layout) ----
        unsigned otA[2][4];
        {
            unsigned xA[2][4];
            #pragma unroll
            for (int kc = 0; kc < 2; kc++)
                ldmA(xA[kc], sbase + XT_OFF + buf*20480 + (m0 + ldrow)*80 + (kc*2 + ldsel)*16);
            float acc[8][4];
            #pragma unroll
            for (int i = 0; i < 8; i++)
                #pragma unroll
                for (int j = 0; j < 4; j++) acc[i][j] = 0.f;
            #pragma unroll
            for (int kc = 0; kc < 2; kc++)
                #pragma unroll
                for (int g4 = 0; g4 < 4; g4++) {
                    unsigned bb[4];
                    ldmBT(bb, sbase + WC_OFF + (kc*16 + ldrow)*144 + (2*g4 + ldsel)*16);
                    mma_f8(acc[2*g4],     xA[kc], bb);
                    mma_f8(acc[2*g4 + 1], xA[kc], bb + 2);
                }
            unsigned pg[8], ph[8];
            #pragma unroll
            for (int i = 0; i < 8; i++) {
                pg[i] = pack_e4m3(acc[i][0]*pr0, acc[i][1]*pr0);
                ph[i] = pack_e4m3(acc[i][2]*pr1, acc[i][3]*pr1);
            }
            *(uint4*)(scw0 + g_*80     + tg*16) = make_uint4(
                pg[0] | (pg[1]<<16), pg[2] | (pg[3]<<16),
                pg[4] | (pg[5]<<16), pg[6] | (pg[7]<<16));
            *(uint4*)(scw0 + (g_+8)*80 + tg*16) = make_uint4(
                ph[0] | (ph[1]<<16), ph[2] | (ph[3]<<16),
                ph[4] | (ph[5]<<16), ph[6] | (ph[7]<<16));
            __syncwarp();
            ldmA(otA[0], scr0 + ldrow*80 +      ldsel*16);
            ldmA(otA[1], scr0 + ldrow*80 + 32 + ldsel*16);
        }

        // ---- prefetch next tile ----
        int nt = tile + GRID_MAIN;
        if (nt < NBLK) stage_tile(smem, buf ^ 1, nt, tid);
        __pipeline_commit();

        // ---- expert loop (parity-alternating scratch, single syncwarp) ----
        float accD[8][4];
        #pragma unroll
        for (int i = 0; i < 8; i++)
            #pragma unroll
            for (int j = 0; j < 4; j++) accD[i][j] = 0.f;

        unsigned w1b = sbase + W1_OFF;
        unsigned w2b = sbase + W2_OFF;
        const float* b1e = b1s;
        int par = 1;
        #pragma unroll 1
        for (int e = 0; e < E_; e++) {
            float ga = ge0[e] * SH, gb = ge1[e] * SH;
            #pragma unroll
            for (int s = 0; s < 3; s++) {
                float acc1[8][4];
                #pragma unroll
                for (int i = 0; i < 8; i++)
                    #pragma unroll
                    for (int j = 0; j < 4; j++) acc1[i][j] = 0.f;
                #pragma unroll
                for (int kc = 0; kc < 2; kc++)
                    #pragma unroll
                    for (int g4 = 0; g4 < 4; g4++) {
                        unsigned bb[4];
                        ldmBT(bb, w1b + (kc*16 + ldrow)*400 + (8*s + 2*g4 + ldsel)*16);
                        mma_f8(acc1[2*g4],     otA[kc], bb);
                        mma_f8(acc1[2*g4 + 1], otA[kc], bb + 2);
                    }
                unsigned pg[8], ph[8];
                #pragma unroll
                for (int i = 0; i < 8; i++) {
                    int j0 = s*64 + 8*i + 2*tg;
                    float2 bv = *(const float2*)&b1e[j0];
                    float v0 = gelu_f(fmaf(acc1[i][0], INV1, bv.x)) * ga;
                    float v1 = gelu_f(fmaf(acc1[i][1], INV1, bv.y)) * ga;
                    float v2 = gelu_f(fmaf(acc1[i][2], INV1, bv.x)) * gb;
                    float v3 = gelu_f(fmaf(acc1[i][3], INV1, bv.y)) * gb;
                    pg[i] = pack_e4m3(v0, v1);
                    ph[i] = pack_e4m3(v2, v3);
                }
                char* scw = scw0 + par*1280;
                unsigned scr = scr0 + par*1280;
                *(uint4*)(scw + g_*80     + tg*16) = make_uint4(
                    pg[0] | (pg[1]<<16), pg[2] | (pg[3]<<16),
                    pg[4] | (pg[5]<<16), pg[6] | (pg[7]<<16));
                *(uint4*)(scw + (g_+8)*80 + tg*16) = make_uint4(
                    ph[0] | (ph[1]<<16), ph[2] | (ph[3]<<16),
                    ph[4] | (ph[5]<<16), ph[6] | (ph[7]<<16));
                __syncwarp();
                unsigned aH[2][4];
                ldmA(aH[0], scr + ldrow*80 +      ldsel*16);
                ldmA(aH[1], scr + ldrow*80 + 32 + ldsel*16);
                #pragma unroll
                for (int kc = 0; kc < 2; kc++) {
                    int kk = 2*s + kc;
                    #pragma unroll
                    for (int g4 = 0; g4 < 4; g4++) {
                        unsigned bb[4];
                        ldmBT(bb, w2b + (kk*16 + ldrow)*144 + (2*g4 + ldsel)*16);
                        mma_f8(accD[2*g4],     aH[kc], bb);
                        mma_f8(accD[2*g4 + 1], aH[kc], bb + 2);
                    }
                }
                par ^= 1;
            }
            w1b += 12800;
            w2b += 13824;
            b1e += JP;
        }

        // ---- epilogue phase 1: y (+bias) -> Ys bf16 [64 ch][528B pitch] ----
        __syncthreads();      // all warps done reading their scratch; Ys overlays it
        {
            char* ys = smem + SC_OFF;
            #pragma unroll
            for (int i = 0; i < 8; i++) {
                int o0 = 8*i + 2*tg, o1 = o0 + 1;
                float b00 = 0.f, b01 = 0.f, b10 = 0.f, b11 = 0.f;
                #pragma unroll
                for (int e = 0; e < E_; e++) {
                    float w0 = b2s[e*C_ + o0], w1v = b2s[e*C_ + o1];
                    b00 += ge0[e]*w0;  b01 += ge0[e]*w1v;
                    b10 += ge1[e]*w0;  b11 += ge1[e]*w1v;
                }
                *(__nv_bfloat16*)(ys + o0*YS_PITCH + ta*2) =
                    __float2bfloat16(fmaf(accD[i][0], INV2, b00));
                *(__nv_bfloat16*)(ys + o1*YS_PITCH + ta*2) =
                    __float2bfloat16(fmaf(accD[i][1], INV2, b01));
                *(__nv_bfloat16*)(ys + o0*YS_PITCH + tb*2) =
                    __float2bfloat16(fmaf(accD[i][2], INV2, b10));
                *(__nv_bfloat16*)(ys + o1*YS_PITCH + tb*2) =
                    __float2bfloat16(fmaf(accD[i][3], INV2, b11));
            }
        }
        __syncthreads();

        // ---- epilogue phase 2: coalesced out = x + Ys ----
        {
            const char* ys = smem + SC_OFF;
            int c  = tid >> 3;            // 0..63
            int t0 = (tid & 7) * 32;      // 32-token strip
            const float* xrow = x   + xbase + (size_t)c*HW_ + hw0 + t0;
            float*       orow = out + xbase + (size_t)c*HW_ + hw0 + t0;
            #pragma unroll
            for (int k = 0; k < 4; k++) {
                uint4 yv = *(const uint4*)(ys + c*YS_PITCH + (t0 + 8*k)*2);
                float4 xa = *(const float4*)(xrow + 8*k);
                float4 xb = *(const float4*)(xrow + 8*k + 4);
                const unsigned yw[4] = { yv.x, yv.y, yv.z, yv.w };
                float yf[8];
                #pragma unroll
                for (int p2 = 0; p2 < 4; p2++) {
                    __nv_bfloat162 h = *(__nv_bfloat162*)&yw[p2];
                    float2 f = __bfloat1622float2(h);
                    yf[2*p2] = f.x; yf[2*p2 + 1] = f.y;
                }
                float4 oa, ob;
                oa.x = xa.x + yf[0]; oa.y = xa.y + yf[1];
                oa.z = xa.z + yf[2]; oa.w = xa.w + yf[3];
                ob.x = xb.x + yf[4]; ob.y = xb.y + yf[5];
                ob.z = xb.z + yf[6]; ob.w = xb.w + yf[7];
                *(float4*)(orow + 8*k)     = oa;
                *(float4*)(orow + 8*k + 4) = ob;
            }
        }

        __pipeline_wait_prior(0);
        __syncthreads();
        buf ^= 1;
    }
}

// ---------------- K_loss ----------------
__global__ void k_loss(float* __restrict__ out, int out_size) {
    __shared__ double imp[E_], lod[E_];
    int warp = threadIdx.x >> 5, lane = threadIdx.x & 31;
    if (warp < E_) {
        double si = 0.0, sl = 0.0;
        for (int blk = lane; blk < GA_NBLK; blk += 32) {
            si += (double)g_impP[blk*E_ + warp];
            sl += (double)g_loadP[blk*E_ + warp];
        }
        #pragma unroll
        for (int o = 16; o; o >>= 1) {
            si += __shfl_down_sync(0xffffffffu, si, o);
            sl += __shfl_down_sync(0xffffffffu, sl, o);
        }
        if (lane == 0) { imp[warp] = si; lod[warp] = sl; }
    }
    __syncthreads();
    if (threadIdx.x == 0) {
        double mi = 0.0, ml = 0.0;
        for (int e = 0; e < E_; e++) { mi += imp[e]; ml += lod[e]; }
        mi *= 0.25; ml *= 0.25;
        double vi = 0.0, vl = 0.0;
        for (int e = 0; e < E_; e++) {
            double d = imp[e] - mi; vi += d*d;
            d = lod[e] - ml;        vl += d*d;
        }
        vi *= 0.25; vl *= 0.25;
        double loss = vi / (mi*mi + 1e-10) + vl / (ml*ml + 1e-10);
        if (out_size > NTOK*C_) out[NTOK*C_] = (float)loss;
    }
}

// ---------------- launch ----------------
extern "C" void kernel_launch(void* const* d_in, const int* in_sizes, int n_in,
                              void* d_out, int out_size) {
    (void)in_sizes; (void)n_in;
    const float* x      = (const float*)d_in[0];
    const float* sp     = (const float*)d_in[2];
    const float* w_lin  = (const float*)d_in[3];
    const float* b_lin  = (const float*)d_in[4];
    const float* w_conv = (const float*)d_in[5];
    const float* w_gate = (const float*)d_in[6];
    const float* w1     = (const float*)d_in[7];
    const float* b1     = (const float*)d_in[8];
    const float* w2     = (const float*)d_in[9];
    const float* b2     = (const float*)d_in[10];
    float* out = (float*)d_out;

    cudaFuncSetAttribute(k_main, cudaFuncAttributeMaxDynamicSharedMemorySize, SMEM_MAIN);

    int prep_total = 32*64 + E_*32*JP + E_*96*64;
    k_prep<<<(prep_total + 255)/256, 256>>>(w_conv, w1, w2);
    k_gate<<<GA_NBLK, GA_TPB>>>(x, w_gate);
    k_emb8<<<B_, 256>>>();
    k_pw<<<B_, 64>>>(w_lin, b_lin);
    k_main<<<GRID_MAIN, TPB, SMEM_MAIN>>>(x, sp, b1, b2, out);
    k_loss<<<1, 128>>>(out, out_size);
}

// round 17
// speedup vs baseline: 1.1645x; 1.1645x over previous
#include <cuda_runtime.h>
#include <cuda_bf16.h>
#include <cuda_pipeline.h>

#define B_   64
#define C_   64
#define HW_  4096
#define NTOK (B_*HW_)          // 262144
#define P_   5
#define E_   4
#define HD_  170
#define JP   192               // padded hidden (6 * 32)
#define TOK  256
#define TPB  512
#define NBLK (NTOK/TOK)        // 1024
#define GRID_MAIN 148
#define GA_NBLK 256            // k_gate blocks (1024 tokens each)

// ---------------- scratch (static __device__, allocation-free) ----------------
__device__ float g_emb[B_*C_];
__device__ float g_pw[B_*P_];
__device__ float g_impP[GA_NBLK*E_];
__device__ float g_loadP[GA_NBLK*E_];
__device__ uint4 g_xT4[(size_t)NTOK*64/16];     // fp8 x^T [tok][64c], 16 MB
__device__ uint4 g_gp4[(size_t)NBLK*256];       // fp32 gates [tile][4][256]
// fp8 weights (scaled x16), packed k-pairs as u16 elements, K-permuted (see k_prep)
__device__ uint4 g_wcP4[32*64*2/16];        // [kp=c/2][o]        (conv B, natural)
__device__ uint4 g_w1P4[E_*32*JP*2/16];     // [e][kp PERM][j 192]
__device__ uint4 g_w2P4[E_*96*64*2/16];     // [e][jp PERM][o]

#define SW  16.0f                // weight scale
#define SOT 128.0f               // OT scale
#define SH  4096.0f              // H scale

__device__ __forceinline__ float gelu_f(float z) {
    float u = z * (0.7978845608028654f + 0.03567740814f * z * z);
    float t;
    asm("tanh.approx.f32 %0, %1;" : "=f"(t) : "f"(u));
    return fmaf(0.5f * z, t, 0.5f * z);
}
__device__ __forceinline__ unsigned pack_e4m3(float lo, float hi) {
    unsigned short u;
    asm("cvt.rn.satfinite.e4m3x2.f32 %0, %1, %2;" : "=h"(u) : "f"(hi), "f"(lo));
    return (unsigned)u;
}
__device__ __forceinline__ unsigned pack4_e4m3(float a, float b, float c, float d) {
    return pack_e4m3(a, b) | (pack_e4m3(c, d) << 16);
}

// ---------------- K0: weight prep (fp32 -> scaled fp8 pairs, K-permuted) --------
__global__ void k_prep(const float* __restrict__ w_conv,
                       const float* __restrict__ w1,
                       const float* __restrict__ w2) {
    int i = blockIdx.x * blockDim.x + threadIdx.x;
    unsigned short* wc = (unsigned short*)g_wcP4;
    unsigned short* w1p = (unsigned short*)g_w1P4;
    unsigned short* w2p = (unsigned short*)g_w2P4;
    const int NWC = 32*64, NW1 = E_*32*JP, NW2 = E_*96*64;
    if (i < NWC) {
        int kp = i >> 6, o = i & 63;    // conv K natural
        wc[i] = (unsigned short)pack_e4m3(w_conv[o*C_ + 2*kp] * SW,
                                          w_conv[o*C_ + 2*kp + 1] * SW);
    } else if (i < NWC + NW1) {
        int r = i - NWC;
        int e = r / (32*JP); int r2 = r % (32*JP);
        int kp = r2 / JP;    int j  = r2 % JP;
        int c0 = 8*(kp & 7) + 2*(kp >> 3);   // permuted source channels
        float lo = (j < HD_) ? w1[((size_t)e*C_ + c0    )*HD_ + j] * SW : 0.f;
        float hi = (j < HD_) ? w1[((size_t)e*C_ + c0 + 1)*HD_ + j] * SW : 0.f;
        w1p[r] = (unsigned short)pack_e4m3(lo, hi);
    } else if (i < NWC + NW1 + NW2) {
        int r = i - NWC - NW1;
        int e = r / (96*64); int r2 = r % (96*64);
        int jp = r2 / 64;    int o  = r2 % 64;
        int s = jp >> 5, t = jp & 31;
        int j0 = s*64 + 8*(t & 7) + 2*(t >> 3);   // permuted source j
        float lo = (j0     < HD_) ? w2[((size_t)e*HD_ + j0    )*C_ + o] * SW : 0.f;
        float hi = (j0 + 1 < HD_) ? w2[((size_t)e*HD_ + j0 + 1)*C_ + o] * SW : 0.f;
        w2p[r] = (unsigned short)pack_e4m3(lo, hi);
    }
}

// ---------------- K_gate: exact gating + loss partials + fp8 x^T ----------------
#define GA_TPB 256
__global__ void __launch_bounds__(GA_TPB) k_gate(
    const float* __restrict__ x, const float* __restrict__ w_gate)
{
    __shared__ float sI[8][E_];
    __shared__ float sC[8][E_];
    const int tid = threadIdx.x, blk = blockIdx.x;
    const int bimg = blk >> 2, hw0 = (blk & 3) * 1024;
    const size_t xbase = (size_t)bimg * (C_*HW_);
    const int tloc = tid * 4;
    const float* xp = x + xbase + hw0 + tloc;

    float l[E_][4];
    #pragma unroll
    for (int e = 0; e < E_; e++)
        #pragma unroll
        for (int k = 0; k < 4; k++) l[e][k] = 0.f;
    unsigned xr[4][16];

    #pragma unroll
    for (int cq = 0; cq < 16; cq++) {
        float4 v0 = *(const float4*)(xp + (size_t)(4*cq    )*HW_);
        float4 v1 = *(const float4*)(xp + (size_t)(4*cq + 1)*HW_);
        float4 v2 = *(const float4*)(xp + (size_t)(4*cq + 2)*HW_);
        float4 v3 = *(const float4*)(xp + (size_t)(4*cq + 3)*HW_);
        float4 w0 = *(const float4*)(w_gate + (4*cq    )*4);
        float4 w1v = *(const float4*)(w_gate + (4*cq + 1)*4);
        float4 w2v = *(const float4*)(w_gate + (4*cq + 2)*4);
        float4 w3 = *(const float4*)(w_gate + (4*cq + 3)*4);
        const float* pv0 = &v0.x; const float* pv1 = &v1.x;
        const float* pv2 = &v2.x; const float* pv3 = &v3.x;
        #pragma unroll
        for (int k = 0; k < 4; k++) {
            float a0 = pv0[k], a1 = pv1[k], a2 = pv2[k], a3 = pv3[k];
            l[0][k] += a0*w0.x + a1*w1v.x + a2*w2v.x + a3*w3.x;
            l[1][k] += a0*w0.y + a1*w1v.y + a2*w2v.y + a3*w3.y;
            l[2][k] += a0*w0.z + a1*w1v.z + a2*w2v.z + a3*w3.z;
            l[3][k] += a0*w0.w + a1*w1v.w + a2*w2v.w + a3*w3.w;
            xr[k][cq] = pack4_e4m3(a0, a1, a2, a3);
        }
    }
    {
        size_t gtok = (size_t)bimg*4096 + hw0 + tloc;
        uint4* dst = g_xT4 + gtok * 4;
        #pragma unroll
        for (int k = 0; k < 4; k++) {
            dst[k*4 + 0] = make_uint4(xr[k][0],  xr[k][1],  xr[k][2],  xr[k][3]);
            dst[k*4 + 1] = make_uint4(xr[k][4],  xr[k][5],  xr[k][6],  xr[k][7]);
            dst[k*4 + 2] = make_uint4(xr[k][8],  xr[k][9],  xr[k][10], xr[k][11]);
            dst[k*4 + 3] = make_uint4(xr[k][12], xr[k][13], xr[k][14], xr[k][15]);
        }
    }
    float gA[E_][4];
    float impA[E_] = {0.f, 0.f, 0.f, 0.f};
    float cntA[E_] = {0.f, 0.f, 0.f, 0.f};
    #pragma unroll
    for (int k = 0; k < 4; k++) {
        float lv[E_] = { l[0][k], l[1][k], l[2][k], l[3][k] };
        float v1m = -1e30f, v2m = -1e30f; int i1 = 0, i2 = 0;
        #pragma unroll
        for (int e = 0; e < E_; e++) {
            if (lv[e] > v1m) { v2m = v1m; i2 = i1; v1m = lv[e]; i1 = e; }
            else if (lv[e] > v2m) { v2m = lv[e]; i2 = e; }
        }
        float g1 = 1.0f / (1.0f + expf(v2m - v1m));
        float g2 = 1.0f - g1;
        #pragma unroll
        for (int e = 0; e < E_; e++)
            gA[e][k] = (e == i1) ? g1 : ((e == i2) ? g2 : 0.f);
        impA[i1] += g1; impA[i2] += g2;
        cntA[i1] += 1.f; cntA[i2] += 1.f;
    }
    {
        int gtok = bimg*4096 + hw0 + tloc;
        int tile = gtok >> 8, tin = gtok & 255;
        float* gpf = (float*)g_gp4 + (size_t)tile*1024 + tin;
        #pragma unroll
        for (int e = 0; e < E_; e++)
            *(float4*)(gpf + e*256) = make_float4(gA[e][0], gA[e][1], gA[e][2], gA[e][3]);
    }
    int warp = tid >> 5, lane = tid & 31;
    #pragma unroll
    for (int e = 0; e < E_; e++) {
        float im = impA[e], cn = cntA[e];
        #pragma unroll
        for (int o = 16; o; o >>= 1) {
            im += __shfl_xor_sync(0xffffffffu, im, o);
            cn += __shfl_xor_sync(0xffffffffu, cn, o);
        }
        if (lane == 0) { sI[warp][e] = im; sC[warp][e] = cn; }
    }
    __syncthreads();
    if (tid < E_) {
        float im = 0.f, cn = 0.f;
        #pragma unroll
        for (int w = 0; w < 8; w++) { im += sI[w][tid]; cn += sC[w][tid]; }
        g_impP[blk*E_ + tid]  = im;
        g_loadP[blk*E_ + tid] = cn;
    }
}

// ---------------- K_emb8: emb from fp8 x^T ----------------
__global__ void __launch_bounds__(256) k_emb8() {
    __shared__ float part[8][64];
    const int b = blockIdx.x, tid = threadIdx.x;
    const int warp = tid >> 5, lane = tid & 31;
    float acc[64];
    #pragma unroll
    for (int c = 0; c < 64; c++) acc[c] = 0.f;
    const uint4* base = g_xT4 + (size_t)b * 4096 * 4;
    for (int row = tid; row < 4096; row += 256) {
        const uint4* rp = base + row*4;
        #pragma unroll
        for (int u4 = 0; u4 < 4; u4++) {
            uint4 v = rp[u4];
            unsigned w[4] = { v.x, v.y, v.z, v.w };
            #pragma unroll
            for (int k = 0; k < 4; k++) {
                unsigned lo16 = w[k] & 0xffffu, hi16 = w[k] >> 16;
                unsigned h2a, h2b;
                asm("cvt.rn.f16x2.e4m3x2 %0, %1;" : "=r"(h2a) : "h"((unsigned short)lo16));
                asm("cvt.rn.f16x2.e4m3x2 %0, %1;" : "=r"(h2b) : "h"((unsigned short)hi16));
                float2 fa = __half22float2(*(__half2*)&h2a);
                float2 fb = __half22float2(*(__half2*)&h2b);
                int c0 = u4*16 + k*4;
                acc[c0]   += fa.x; acc[c0+1] += fa.y;
                acc[c0+2] += fb.x; acc[c0+3] += fb.y;
            }
        }
    }
    #pragma unroll
    for (int c = 0; c < 64; c++) {
        float s = acc[c];
        #pragma unroll
        for (int o = 16; o; o >>= 1) s += __shfl_xor_sync(0xffffffffu, s, o);
        if (lane == 0) part[warp][c] = s;
    }
    __syncthreads();
    if (tid < 64) {
        float s = 0.f;
        #pragma unroll
        for (int w = 0; w < 8; w++) s += part[w][tid];
        g_emb[b*64 + tid] = s * (1.0f / HW_);
    }
}

// ---------------- K2: pw ----------------
__global__ void k_pw(const float* __restrict__ w_lin, const float* __restrict__ b_lin) {
    int b = blockIdx.x, c = threadIdx.x;   // 64 threads
    __shared__ float red[2][P_];
    float e = g_emb[b*C_ + c];
    float lg[P_];
    #pragma unroll
    for (int p = 0; p < P_; p++) lg[p] = e * w_lin[c*P_ + p];
    #pragma unroll
    for (int o = 16; o; o >>= 1)
        #pragma unroll
        for (int p = 0; p < P_; p++) lg[p] += __shfl_xor_sync(0xffffffffu, lg[p], o);
    if ((c & 31) == 0)
        #pragma unroll
        for (int p = 0; p < P_; p++) red[c >> 5][p] = lg[p];
    __syncthreads();
    if (c == 0) {
        float v[P_];
        #pragma unroll
        for (int p = 0; p < P_; p++) v[p] = red[0][p] + red[1][p] + b_lin[p];
        float mx = v[0];
        #pragma unroll
        for (int p = 1; p < P_; p++) mx = fmaxf(mx, v[p]);
        float s = 0.f;
        #pragma unroll
        for (int p = 0; p < P_; p++) { v[p] = expf(v[p] - mx); s += v[p]; }
        float inv = 1.0f / s;
        #pragma unroll
        for (int p = 0; p < P_; p++) g_pw[b*P_ + p] = v[p] * inv;
    }
}

// ---------------- mma helpers ----------------
__device__ __forceinline__ void mma_f8(float* c, const unsigned* a, const unsigned* b) {
    asm volatile(
        "mma.sync.aligned.m16n8k32.row.col.f32.e4m3.e4m3.f32 "
        "{%0,%1,%2,%3},{%4,%5,%6,%7},{%8,%9},{%0,%1,%2,%3};\n"
        : "+f"(c[0]), "+f"(c[1]), "+f"(c[2]), "+f"(c[3])
        : "r"(a[0]), "r"(a[1]), "r"(a[2]), "r"(a[3]), "r"(b[0]), "r"(b[1]));
}
__device__ __forceinline__ void ldmA(unsigned* a, unsigned addr) {
    asm volatile("ldmatrix.sync.aligned.m8n8.x4.shared.b16 {%0,%1,%2,%3},[%4];\n"
        : "=r"(a[0]), "=r"(a[1]), "=r"(a[2]), "=r"(a[3]) : "r"(addr));
}
__device__ __forceinline__ void ldmBT(unsigned* b, unsigned addr) {
    asm volatile("ldmatrix.sync.aligned.m8n8.x4.trans.shared.b16 {%0,%1,%2,%3},[%4];\n"
        : "=r"(b[0]), "=r"(b[1]), "=r"(b[2]), "=r"(b[3]) : "r"(addr));
}

// gemm1 for one 64-j slice: acc1 = OT @ W1_slice
__device__ __forceinline__ void do_gemm1(
    float acc1[8][4], unsigned w1b, int s, const unsigned otA[2][4],
    unsigned ldrow, unsigned ldsel)
{
    #pragma unroll
    for (int i = 0; i < 8; i++)
        #pragma unroll
        for (int j = 0; j < 4; j++) acc1[i][j] = 0.f;
    #pragma unroll
    for (int kc = 0; kc < 2; kc++)
        #pragma unroll
        for (int g4 = 0; g4 < 4; g4++) {
            unsigned bb[4];
            ldmBT(bb, w1b + (kc*16 + ldrow)*400 + (8*s + 2*g4 + ldsel)*16);
            mma_f8(acc1[2*g4],     otA[kc], bb);
            mma_f8(acc1[2*g4 + 1], otA[kc], bb + 2);
        }
}

__global__ void __launch_bounds__(TPB, 1) k_main(
    const float* __restrict__ x, const float* __restrict__ sp,
    const float* __restrict__ b1, const float* __restrict__ b2,
    float* __restrict__ out)
{
    // ---------------- smem layout (bytes) ----------------
    #define XT_OFF  0               // 2 x (256 rows * 80B) = 40960
    #define GT_OFF  40960           // 2 x 4096 (gates)
    #define W1_OFF  49152           // 4 x 12800
    #define W2_OFF  100352          // 4 x 13824
    #define WC_OFF  155648          // 4608
    #define B1_OFF  160256          // 3072
    #define B2_OFF  163328          // 1024
    #define SC_OFF  164352          // per-warp scratch: 16 x 2 x 1280 = 40960
    #define SMEM_MAIN 205312
    extern __shared__ char smem[];
    unsigned sbase = (unsigned)__cvta_generic_to_shared(smem);
    float* b1s = (float*)(smem + B1_OFF);
    float* b2s = (float*)(smem + B2_OFF);

    const int tid  = threadIdx.x;
    const int lane = tid & 31, warp = tid >> 5;
    const int r = lane & 7, q = lane >> 3;
    const int g_ = lane >> 2, tg = lane & 3;
    const int m0 = warp * 16, ta = m0 + g_, tb = ta + 8;
    const unsigned scr0 = sbase + SC_OFF + warp*2560;
    char* scw0 = smem + SC_OFF + warp*2560;
    const unsigned ldrow = (unsigned)(r + (q&1)*8);
    const unsigned ldsel = (unsigned)(q >> 1);

    // ---- one-time staging: all weights + first tile ----
    for (int u = tid; u < 32*8; u += TPB) {
        int row = u >> 3, un = u & 7;
        __pipeline_memcpy_async(smem + WC_OFF + row*144 + un*16, g_wcP4 + u, 16);
    }
    for (int u = tid; u < E_*32*24; u += TPB) {
        int e = u / (32*24), v = u % (32*24);
        int row = v / 24, un = v % 24;
        __pipeline_memcpy_async(smem + W1_OFF + e*12800 + row*400 + un*16, g_w1P4 + u, 16);
    }
    for (int u = tid; u < E_*96*8; u += TPB) {
        int e = u / (96*8), v = u % (96*8);
        int row = v >> 3, un = v & 7;
        __pipeline_memcpy_async(smem + W2_OFF + e*13824 + row*144 + un*16, g_w2P4 + u, 16);
    }
    // first tile stage
    {
        const uint4* src = g_xT4 + (size_t)blockIdx.x * (TOK*4);
        for (int u = tid; u < TOK*4; u += TPB) {
            int row = u >> 2, un = u & 3;
            __pipeline_memcpy_async(smem + XT_OFF + row*80 + un*16, src + u, 16);
        }
        const uint4* gsrc = g_gp4 + (size_t)blockIdx.x * 256;
        for (int u = tid; u < 256; u += TPB)
            __pipeline_memcpy_async(smem + GT_OFF + u*16, gsrc + u, 16);
    }
    __pipeline_commit();
    for (int i = tid; i < E_*JP; i += TPB) {
        int e = i / JP, j = i % JP;
        b1s[i] = (j < HD_) ? b1[e*HD_ + j] : 0.f;
    }
    if (tid < E_*C_) b2s[tid] = b2[tid];
    __pipeline_wait_prior(0);
    __syncthreads();

    const float INV1 = 1.0f / (SOT * SW);
    const float INV2 = 1.0f / (SH * SW);

    int buf = 0;
    for (int tile = blockIdx.x; tile < NBLK; tile += GRID_MAIN) {
        const int bimg = tile >> 4;
        const int hw0  = (tile & 15) * TOK;
        const size_t xbase = (size_t)bimg * (C_*HW_);
        const float* gtp = (float*)(smem + GT_OFF + buf*4096);

        float ge0[E_], ge1[E_];
        #pragma unroll
        for (int e = 0; e < E_; e++) {
            ge0[e] = gtp[e*TOK + ta];
            ge1[e] = gtp[e*TOK + tb];
        }
        float pr0 = 0.f, pr1 = 0.f;
        #pragma unroll
        for (int p = 0; p < P_; p++) {
            float pwv = g_pw[bimg*P_ + p];
            pr0 = fmaf(pwv, sp[p*HW_ + hw0 + ta], pr0);
            pr1 = fmaf(pwv, sp[p*HW_ + hw0 + tb], pr1);
        }
        pr0 *= (SOT / SW);
        pr1 *= (SOT / SW);

        // ---- conv (writes scratch parity 0, permuted K layout) ----
        unsigned otA[2][4];
        {
            unsigned xA[2][4];
            #pragma unroll
            for (int kc = 0; kc < 2; kc++)
                ldmA(xA[kc], sbase + XT_OFF + buf*20480 + (m0 + ldrow)*80 + (kc*2 + ldsel)*16);
            float acc[8][4];
            #pragma unroll
            for (int i = 0; i < 8; i++)
                #pragma unroll
                for (int j = 0; j < 4; j++) acc[i][j] = 0.f;
            #pragma unroll
            for (int kc = 0; kc < 2; kc++)
                #pragma unroll
                for (int g4 = 0; g4 < 4; g4++) {
                    unsigned bb[4];
                    ldmBT(bb, sbase + WC_OFF + (kc*16 + ldrow)*144 + (2*g4 + ldsel)*16);
                    mma_f8(acc[2*g4],     xA[kc], bb);
                    mma_f8(acc[2*g4 + 1], xA[kc], bb + 2);
                }
            unsigned pg[8], ph[8];
            #pragma unroll
            for (int i = 0; i < 8; i++) {
                pg[i] = pack_e4m3(acc[i][0]*pr0, acc[i][1]*pr0);
                ph[i] = pack_e4m3(acc[i][2]*pr1, acc[i][3]*pr1);
            }
            *(uint4*)(scw0 + g_*80     + tg*16) = make_uint4(
                pg[0] | (pg[1]<<16), pg[2] | (pg[3]<<16),
                pg[4] | (pg[5]<<16), pg[6] | (pg[7]<<16));
            *(uint4*)(scw0 + (g_+8)*80 + tg*16) = make_uint4(
                ph[0] | (ph[1]<<16), ph[2] | (ph[3]<<16),
                ph[4] | (ph[5]<<16), ph[6] | (ph[7]<<16));
            __syncwarp();
            ldmA(otA[0], scr0 + ldrow*80 +      ldsel*16);
            ldmA(otA[1], scr0 + ldrow*80 + 32 + ldsel*16);
        }

        // ---- prefetch next tile ----
        int nt = tile + GRID_MAIN;
        if (nt < NBLK) {
            const uint4* src = g_xT4 + (size_t)nt * (TOK*4);
            int nbuf = buf ^ 1;
            for (int u = tid; u < TOK*4; u += TPB) {
                int row = u >> 2, un = u & 3;
                __pipeline_memcpy_async(smem + XT_OFF + nbuf*20480 + row*80 + un*16, src + u, 16);
            }
            const uint4* gsrc = g_gp4 + (size_t)nt * 256;
            for (int u = tid; u < 256; u += TPB)
                __pipeline_memcpy_async(smem + GT_OFF + nbuf*4096 + u*16, gsrc + u, 16);
        }
        __pipeline_commit();

        // ---- software-pipelined 12-slice expert chain ----
        float accD[8][4];
        #pragma unroll
        for (int i = 0; i < 8; i++)
            #pragma unroll
            for (int j = 0; j < 4; j++) accD[i][j] = 0.f;

        float acc1[8][4];
        // producer state (slice being gemm1'd) and consumer state (slice in epi/gemm2)
        int sN = 0;  unsigned w1bN = sbase + W1_OFF;
        int sC = 0;  unsigned w2bC = sbase + W2_OFF;
        int eC = 0;
        const float* b1C = b1s;
        float gaC = ge0[0] * SH, gbC = ge1[0] * SH;
        // prologue: gemm1 slice 0
        do_gemm1(acc1, w1bN, sN, otA, ldrow, ldsel);
        int par = 1;
        #pragma unroll 1
        for (int n = 0; n < 12; n++) {
            // epi(slice n): acc1 -> fp8 -> scratch[par]; ldm aH
            {
                unsigned pg[8], ph[8];
                #pragma unroll
                for (int i = 0; i < 8; i++) {
                    int j0 = sC*64 + 8*i + 2*tg;
                    float2 bv = *(const float2*)&b1C[j0];
                    float v0 = gelu_f(fmaf(acc1[i][0], INV1, bv.x)) * gaC;
                    float v1 = gelu_f(fmaf(acc1[i][1], INV1, bv.y)) * gaC;
                    float v2 = gelu_f(fmaf(acc1[i][2], INV1, bv.x)) * gbC;
                    float v3 = gelu_f(fmaf(acc1[i][3], INV1, bv.y)) * gbC;
                    pg[i] = pack_e4m3(v0, v1);
                    ph[i] = pack_e4m3(v2, v3);
                }
                char* scw = scw0 + par*1280;
                *(uint4*)(scw + g_*80     + tg*16) = make_uint4(
                    pg[0] | (pg[1]<<16), pg[2] | (pg[3]<<16),
                    pg[4] | (pg[5]<<16), pg[6] | (pg[7]<<16));
                *(uint4*)(scw + (g_+8)*80 + tg*16) = make_uint4(
                    ph[0] | (ph[1]<<16), ph[2] | (ph[3]<<16),
                    ph[4] | (ph[5]<<16), ph[6] | (ph[7]<<16));
            }
            __syncwarp();
            unsigned aH[2][4];
            {
                unsigned scr = scr0 + par*1280;
                ldmA(aH[0], scr + ldrow*80 +      ldsel*16);
                ldmA(aH[1], scr + ldrow*80 + 32 + ldsel*16);
            }
            // gemm1(slice n+1): independent mma stream covers the LDSM latency
            if (n < 11) {
                sN++;
                if (sN == 3) { sN = 0; w1bN += 12800; }
                do_gemm1(acc1, w1bN, sN, otA, ldrow, ldsel);
            }
            // gemm2(slice n): accD += aH @ W2_slice
            #pragma unroll
            for (int kc = 0; kc < 2; kc++) {
                int kk = 2*sC + kc;
                #pragma unroll
                for (int g4 = 0; g4 < 4; g4++) {
                    unsigned bb[4];
                    ldmBT(bb, w2bC + (kk*16 + ldrow)*144 + (2*g4 + ldsel)*16);
                    mma_f8(accD[2*g4],     aH[kc], bb);
                    mma_f8(accD[2*g4 + 1], aH[kc], bb + 2);
                }
            }
            // advance consumer
            sC++;
            if (sC == 3) {
                sC = 0; w2bC += 13824; b1C += JP;
                if (eC < E_ - 1) {
                    eC++;
                    gaC = ge0[eC] * SH;
                    gbC = ge1[eC] * SH;
                }
            }
            par ^= 1;
        }

        // ---- epilogue: out = x + y + sum_e gates*b2 (R15 form) ----
        #pragma unroll
        for (int i = 0; i < 8; i++) {
            int o0 = 8*i + 2*tg, o1 = o0 + 1;
            float b00 = 0.f, b01 = 0.f, b10 = 0.f, b11 = 0.f;
            #pragma unroll
            for (int e = 0; e < E_; e++) {
                float w0 = b2s[e*C_ + o0], w1v = b2s[e*C_ + o1];
                b00 += ge0[e]*w0;  b01 += ge0[e]*w1v;
                b10 += ge1[e]*w0;  b11 += ge1[e]*w1v;
            }
            size_t p0 = xbase + (size_t)o0*HW_ + hw0;
            size_t p1 = xbase + (size_t)o1*HW_ + hw0;
            out[p0 + ta] = x[p0 + ta] + fmaf(accD[i][0], INV2, b00);
            out[p1 + ta] = x[p1 + ta] + fmaf(accD[i][1], INV2, b01);
            out[p0 + tb] = x[p0 + tb] + fmaf(accD[i][2], INV2, b10);
            out[p1 + tb] = x[p1 + tb] + fmaf(accD[i][3], INV2, b11);
        }

        __pipeline_wait_prior(0);
        __syncthreads();
        buf ^= 1;
    }
}

// ---------------- K_loss ----------------
__global__ void k_loss(float* __restrict__ out, int out_size) {
    __shared__ double imp[E_], lod[E_];
    int warp = threadIdx.x >> 5, lane = threadIdx.x & 31;
    if (warp < E_) {
        double si = 0.0, sl = 0.0;
        for (int blk = lane; blk < GA_NBLK; blk += 32) {
            si += (double)g_impP[blk*E_ + warp];
            sl += (double)g_loadP[blk*E_ + warp];
        }
        #pragma unroll
        for (int o = 16; o; o >>= 1) {
            si += __shfl_down_sync(0xffffffffu, si, o);
            sl += __shfl_down_sync(0xffffffffu, sl, o);
        }
        if (lane == 0) { imp[warp] = si; lod[warp] = sl; }
    }
    __syncthreads();
    if (threadIdx.x == 0) {
        double mi = 0.0, ml = 0.0;
        for (int e = 0; e < E_; e++) { mi += imp[e]; ml += lod[e]; }
        mi *= 0.25; ml *= 0.25;
        double vi = 0.0, vl = 0.0;
        for (int e = 0; e < E_; e++) {
            double d = imp[e] - mi; vi += d*d;
            d = lod[e] - ml;        vl += d*d;
        }
        vi *= 0.25; vl *= 0.25;
        double loss = vi / (mi*mi + 1e-10) + vl / (ml*ml + 1e-10);
        if (out_size > NTOK*C_) out[NTOK*C_] = (float)loss;
    }
}

// ---------------- launch ----------------
extern "C" void kernel_launch(void* const* d_in, const int* in_sizes, int n_in,
                              void* d_out, int out_size) {
    (void)in_sizes; (void)n_in;
    const float* x      = (const float*)d_in[0];
    const float* sp     = (const float*)d_in[2];
    const float* w_lin  = (const float*)d_in[3];
    const float* b_lin  = (const float*)d_in[4];
    const float* w_conv = (const float*)d_in[5];
    const float* w_gate = (const float*)d_in[6];
    const float* w1     = (const float*)d_in[7];
    const float* b1     = (const float*)d_in[8];
    const float* w2     = (const float*)d_in[9];
    const float* b2     = (const float*)d_in[10];
    float* out = (float*)d_out;

    cudaFuncSetAttribute(k_main, cudaFuncAttributeMaxDynamicSharedMemorySize, SMEM_MAIN);

    int prep_total = 32*64 + E_*32*JP + E_*96*64;
    k_prep<<<(prep_total + 255)/256, 256>>>(w_conv, w1, w2);
    k_gate<<<GA_NBLK, GA_TPB>>>(x, w_gate);
    k_emb8<<<B_, 256>>>();
    k_pw<<<B_, 64>>>(w_lin, b_lin);
    k_main<<<GRID_MAIN, TPB, SMEM_MAIN>>>(x, sp, b1, b2, out);
    k_loss<<<1, 128>>>(out, out_size);
}